// round 9
// baseline (speedup 1.0000x reference)
#include <cuda_runtime.h>

// Problem constants (shapes fixed by the dataset)
#define F_IN   128
#define F_OUT  64
#define MAX_N  50000

#define GEMM_ROWS 32          // rows of x per block
#define GEMM_THREADS 256      // 32 rows x 8 col-groups

// Scratch: support = (x @ W) * t[:,None]
__device__ __align__(16) float g_support[MAX_N * F_OUT];
// Index dtype flag: 1 if src/dst are int64, 0 if int32
__device__ int g_idx_is64;

// ---------------------------------------------------------------------------
// Kernel 0: detect index dtype. If the buffer is int64, every 64-bit value is
// a valid node id in [0, n). If it is int32, the fused (lo,hi) pairs of random
// indices are >= 2^32 almost surely. Deterministic for fixed inputs.
// ---------------------------------------------------------------------------
__global__ void detect_idx_kernel(const long long* __restrict__ src_as_i64,
                                  int n, int e)
{
    int cnt = (e < 64) ? e : 64;
    int ok = 1;
    for (int i = 0; i < cnt; i++) {
        long long v = src_as_i64[i];
        if (v < 0 || v >= (long long)n) { ok = 0; break; }
    }
    g_idx_is64 = ok;
}

// ---------------------------------------------------------------------------
// Kernel 1: support[r, :] = (x[r, :] @ W) * t[r]
// 256 threads -> 32 rows x 8 col-groups (8 cols each). Weight (32 KB) fully
// in smem; x tile in two K-halves of 64 (padded to 72 for conflict-free LDS).
// ---------------------------------------------------------------------------
__global__ void __launch_bounds__(GEMM_THREADS)
gemm_scale_kernel(const float* __restrict__ x,
                  const float* __restrict__ w,
                  const float* __restrict__ t,
                  int n)
{
    __shared__ float ws[F_IN * F_OUT];        // 32768 B
    __shared__ float xs[GEMM_ROWS][72];       // 9216 B

    const int tid = threadIdx.x;
    const int row0 = blockIdx.x * GEMM_ROWS;

    // Weight -> smem, vectorized
    {
        const float4* wsrc = (const float4*)w;
        float4* wdst = (float4*)ws;
        #pragma unroll
        for (int i = 0; i < (F_IN * F_OUT / 4) / GEMM_THREADS; i++)
            wdst[tid + i * GEMM_THREADS] = wsrc[tid + i * GEMM_THREADS];
    }

    const int ri = tid >> 3;        // row within tile
    const int cj = tid & 7;         // col group
    const int c0 = cj * 8;
    const int row = row0 + ri;

    float acc[8];
    #pragma unroll
    for (int j = 0; j < 8; j++) acc[j] = 0.0f;

    #pragma unroll
    for (int p = 0; p < 2; p++) {
        __syncthreads();
        #pragma unroll
        for (int j = 0; j < 2; j++) {
            int f  = tid + j * GEMM_THREADS;
            int rr = f >> 4;
            int k4 = f & 15;
            int grow = row0 + rr;
            float4 v = make_float4(0.f, 0.f, 0.f, 0.f);
            if (grow < n)
                v = *(const float4*)(x + (long long)grow * F_IN + p * 64 + k4 * 4);
            xs[rr][k4 * 4 + 0] = v.x;
            xs[rr][k4 * 4 + 1] = v.y;
            xs[rr][k4 * 4 + 2] = v.z;
            xs[rr][k4 * 4 + 3] = v.w;
        }
        __syncthreads();

        const float* wp = ws + p * 64 * F_OUT + c0;
        #pragma unroll 8
        for (int k = 0; k < 64; k++) {
            float xv = xs[ri][k];
            const float* wk = wp + k * F_OUT;
            #pragma unroll
            for (int j = 0; j < 8; j++)
                acc[j] = fmaf(xv, wk[j], acc[j]);
        }
    }

    if (row < n) {
        float tv = t[row];
        float4 o0 = make_float4(acc[0] * tv, acc[1] * tv, acc[2] * tv, acc[3] * tv);
        float4 o1 = make_float4(acc[4] * tv, acc[5] * tv, acc[6] * tv, acc[7] * tv);
        float4* op = (float4*)(g_support + (long long)row * F_OUT + c0);
        op[0] = o0;
        op[1] = o1;
    }
}

// ---------------------------------------------------------------------------
// Kernel 2: out[r, c] = bias[c]
// ---------------------------------------------------------------------------
__global__ void init_bias_kernel(float* __restrict__ out,
                                 const float* __restrict__ bias,
                                 long long total)
{
    long long i = (long long)blockIdx.x * blockDim.x + threadIdx.x;
    if (i < total)
        out[i] = bias[(int)(i & (F_OUT - 1))];
}

// ---------------------------------------------------------------------------
// Kernel 3: out[dst[e], :] += support[src[e], :] * edge_vals[e]
// 16 threads per edge (one float4 chunk each); red.global.add.v4.f32 ->
// one L2 atomic per 16 bytes. Index dtype resolved via g_idx_is64.
// ---------------------------------------------------------------------------
__global__ void __launch_bounds__(256)
scatter_kernel(const void* __restrict__ src_raw,
               const void* __restrict__ dst_raw,
               const float* __restrict__ ev,
               float* __restrict__ out,
               long long total)
{
    long long tid = (long long)blockIdx.x * blockDim.x + threadIdx.x;
    if (tid >= total) return;

    int e = (int)(tid >> 4);
    int q = (int)(tid & 15);

    int s, d;
    if (g_idx_is64) {
        s = (int)((const long long*)src_raw)[e];
        d = (int)((const long long*)dst_raw)[e];
    } else {
        s = ((const int*)src_raw)[e];
        d = ((const int*)dst_raw)[e];
    }
    float v = ev[e];

    float4 m = __ldg((const float4*)(g_support + (long long)s * F_OUT) + q);
    m.x *= v; m.y *= v; m.z *= v; m.w *= v;

    float* addr = out + (long long)d * F_OUT + q * 4;
    asm volatile("red.global.add.v4.f32 [%0], {%1, %2, %3, %4};"
                 :: "l"(addr), "f"(m.x), "f"(m.y), "f"(m.z), "f"(m.w)
                 : "memory");
}

// ---------------------------------------------------------------------------
// Inputs (metadata order):
//   0: x [N, F_IN] f32   1: t [N] f32   2: src [E]   3: dst [E]
//   4: edge_vals [E] f32 5: weight [F_IN, F_OUT] f32 6: bias [F_OUT] f32
// Output: [N, F_OUT] f32
// ---------------------------------------------------------------------------
extern "C" void kernel_launch(void* const* d_in, const int* in_sizes, int n_in,
                              void* d_out, int out_size)
{
    const float* x    = (const float*)d_in[0];
    const float* t    = (const float*)d_in[1];
    const void*  src  = d_in[2];
    const void*  dst  = d_in[3];
    const float* ev   = (const float*)d_in[4];
    const float* w    = (const float*)d_in[5];
    const float* bias = (const float*)d_in[6];
    float*       out  = (float*)d_out;

    const int n = in_sizes[1];   // N
    const int e = in_sizes[2];   // E

    // 0) resolve index dtype (cheap, deterministic)
    detect_idx_kernel<<<1, 1>>>((const long long*)src, n, e);

    // 1) support = (x @ W) * t[:,None]
    int gemm_blocks = (n + GEMM_ROWS - 1) / GEMM_ROWS;
    gemm_scale_kernel<<<gemm_blocks, GEMM_THREADS>>>(x, w, t, n);

    // 2) out = bias broadcast
    long long out_total = (long long)n * F_OUT;
    int init_blocks = (int)((out_total + 255) / 256);
    init_bias_kernel<<<init_blocks, 256>>>(out, bias, out_total);

    // 3) scatter-add
    long long scat_total = (long long)e * 16;
    int scat_blocks = (int)((scat_total + 255) / 256);
    scatter_kernel<<<scat_blocks, 256>>>(src, dst, ev, out, scat_total);
}

// round 12
// speedup vs baseline: 1.7648x; 1.7648x over previous
#include <cuda_runtime.h>

// Problem constants (dataset-fixed shapes)
#define F_IN   128
#define F_OUT  64
#define MAX_N  50000
#define MAX_E  800000

#define GEMM_ROWS   128        // rows of x per block
#define GEMM_THREADS 256

// ---------------- static scratch (no allocs allowed) ----------------
__device__ __align__(16) float g_support[MAX_N * F_OUT]; // (x@W)*t
__device__ __align__(16) int2  g_edges[MAX_E];           // (src, ev bits) bucketed by dst
__device__ int g_count[MAX_N];                           // per-dst degree
__device__ int g_eoff[MAX_N];                            // exclusive offsets
__device__ int g_cursor[MAX_N];                          // fill cursors
__device__ int g_bsum[64];                               // scan block sums
__device__ int g_boff[64];                               // scan block offsets
__device__ int g_idx_is64;                               // index dtype flag

// ---------------------------------------------------------------------------
// K0: index dtype detect (parallel, ~1us). If buffer is int32, fused 64-bit
// reads of random indices are >= 2^32 almost surely.
// ---------------------------------------------------------------------------
__global__ void detect_idx_kernel(const long long* __restrict__ p, int n, int e)
{
    int cnt = (e < 32) ? e : 32;
    bool bad = false;
    if ((int)threadIdx.x < cnt) {
        long long v = p[threadIdx.x];
        bad = (v < 0 || v >= (long long)n);
    }
    unsigned m = __ballot_sync(0xffffffffu, bad);
    if (threadIdx.x == 0) g_idx_is64 = (m == 0u) ? 1 : 0;
}

__device__ __forceinline__ int load_idx(const void* p, int i)
{
    return g_idx_is64 ? (int)((const long long*)p)[i] : ((const int*)p)[i];
}

// ---------------------------------------------------------------------------
// K1: zero per-dst counts
// ---------------------------------------------------------------------------
__global__ void zero_count_kernel(int n)
{
    int i = blockIdx.x * blockDim.x + threadIdx.x;
    if (i < n) g_count[i] = 0;
}

// ---------------------------------------------------------------------------
// K2: GEMM + row-scale: support[r,:] = (x[r,:] @ W) * t[r]
// 256 threads -> 32 row-groups x 8 col-groups; 4 rows x 8 cols per thread.
// K processed in 4 phases of 32; weight tile 8KB, x tile 16.5KB in smem.
// Inner loop: 6 LDS + 32 FFMA per k.
// ---------------------------------------------------------------------------
__global__ void __launch_bounds__(GEMM_THREADS)
gemm_scale_kernel(const float* __restrict__ x,
                  const float* __restrict__ w,
                  const float* __restrict__ t,
                  int n)
{
    __shared__ float ws[32 * F_OUT];           // 8 KB   (one K-phase of W)
    __shared__ float xs[GEMM_ROWS * 33];       // 16.9 KB (pad 33 -> conflict-free)

    const int tid  = threadIdx.x;
    const int row0 = blockIdx.x * GEMM_ROWS;
    const int cj = tid & 7;          // col group (8 cols)
    const int rg = tid >> 3;         // row group (4 rows)
    const int c0 = cj * 8;

    float acc[4][8];
    #pragma unroll
    for (int i = 0; i < 4; i++)
        #pragma unroll
        for (int j = 0; j < 8; j++) acc[i][j] = 0.0f;

    #pragma unroll
    for (int p = 0; p < 4; p++) {
        __syncthreads();
        // load W phase: 32x64 floats = 512 float4, 2 per thread
        {
            const float4* wsrc = (const float4*)(w + p * 32 * F_OUT);
            float4* wdst = (float4*)ws;
            wdst[tid]       = wsrc[tid];
            wdst[tid + 256] = wsrc[tid + 256];
        }
        // load x phase: 128 rows x 32 cols = 1024 float4, 4 per thread
        #pragma unroll
        for (int i = 0; i < 4; i++) {
            int f  = tid + i * 256;
            int rr = f >> 3;        // 0..127
            int k4 = f & 7;         // 0..7
            int grow = row0 + rr;
            float4 v = make_float4(0.f, 0.f, 0.f, 0.f);
            if (grow < n)
                v = *(const float4*)(x + (long long)grow * F_IN + p * 32 + k4 * 4);
            float* d = xs + rr * 33 + k4 * 4;
            d[0] = v.x; d[1] = v.y; d[2] = v.z; d[3] = v.w;
        }
        __syncthreads();

        #pragma unroll 4
        for (int k = 0; k < 32; k++) {
            float4 w0 = *(const float4*)(ws + k * F_OUT + c0);
            float4 w1 = *(const float4*)(ws + k * F_OUT + c0 + 4);
            #pragma unroll
            for (int i = 0; i < 4; i++) {
                float xv = xs[(rg * 4 + i) * 33 + k];
                acc[i][0] = fmaf(xv, w0.x, acc[i][0]);
                acc[i][1] = fmaf(xv, w0.y, acc[i][1]);
                acc[i][2] = fmaf(xv, w0.z, acc[i][2]);
                acc[i][3] = fmaf(xv, w0.w, acc[i][3]);
                acc[i][4] = fmaf(xv, w1.x, acc[i][4]);
                acc[i][5] = fmaf(xv, w1.y, acc[i][5]);
                acc[i][6] = fmaf(xv, w1.z, acc[i][6]);
                acc[i][7] = fmaf(xv, w1.w, acc[i][7]);
            }
        }
    }

    #pragma unroll
    for (int i = 0; i < 4; i++) {
        int row = row0 + rg * 4 + i;
        if (row < n) {
            float tv = t[row];
            float4 o0 = make_float4(acc[i][0]*tv, acc[i][1]*tv, acc[i][2]*tv, acc[i][3]*tv);
            float4 o1 = make_float4(acc[i][4]*tv, acc[i][5]*tv, acc[i][6]*tv, acc[i][7]*tv);
            float4* op = (float4*)(g_support + (long long)row * F_OUT + c0);
            op[0] = o0;
            op[1] = o1;
        }
    }
}

// ---------------------------------------------------------------------------
// K3: per-dst histogram
// ---------------------------------------------------------------------------
__global__ void hist_kernel(const void* __restrict__ dst, int e)
{
    int i = blockIdx.x * blockDim.x + threadIdx.x;
    if (i < e) atomicAdd(&g_count[load_idx(dst, i)], 1);
}

// ---------------------------------------------------------------------------
// K4-K6: exclusive scan of g_count -> g_eoff (two-level)
// ---------------------------------------------------------------------------
__global__ void scan1_kernel(int n)
{
    __shared__ int sm[1024];
    int i = blockIdx.x * 1024 + threadIdx.x;
    int c = (i < n) ? g_count[i] : 0;
    sm[threadIdx.x] = c;
    __syncthreads();
    #pragma unroll
    for (int off = 1; off < 1024; off <<= 1) {
        int v = (threadIdx.x >= (unsigned)off) ? sm[threadIdx.x - off] : 0;
        __syncthreads();
        sm[threadIdx.x] += v;
        __syncthreads();
    }
    int incl = sm[threadIdx.x];
    if (i < n) g_eoff[i] = incl - c;          // block-local exclusive
    if (threadIdx.x == 1023) g_bsum[blockIdx.x] = incl;
}

__global__ void scan2_kernel(int nb)
{
    if (threadIdx.x == 0) {
        int run = 0;
        for (int b = 0; b < nb; b++) { g_boff[b] = run; run += g_bsum[b]; }
    }
}

__global__ void scan3_kernel(int n)
{
    int i = blockIdx.x * blockDim.x + threadIdx.x;
    if (i < n) {
        int e0 = g_eoff[i] + g_boff[i >> 10];
        g_eoff[i]   = e0;
        g_cursor[i] = e0;
    }
}

// ---------------------------------------------------------------------------
// K7: bucket edges by dst: g_edges[slot] = (src, ev)
// ---------------------------------------------------------------------------
__global__ void reorder_kernel(const void* __restrict__ src,
                               const void* __restrict__ dst,
                               const float* __restrict__ ev,
                               int e)
{
    int i = blockIdx.x * blockDim.x + threadIdx.x;
    if (i >= e) return;
    int s = load_idx(src, i);
    int d = load_idx(dst, i);
    int pos = atomicAdd(&g_cursor[d], 1);
    g_edges[pos] = make_int2(s, __float_as_int(ev[i]));
}

// ---------------------------------------------------------------------------
// K8: gather-reduce. One warp per dst node; lane owns 2 cols (float2).
// No atomics: out[d,:] = sum_e ev_e * support[src_e,:] + bias.
// ---------------------------------------------------------------------------
__global__ void __launch_bounds__(256)
gather_kernel(float* __restrict__ out,
              const float* __restrict__ bias,
              int n)
{
    int node = blockIdx.x * 8 + (threadIdx.x >> 5);
    if (node >= n) return;
    int lane = threadIdx.x & 31;

    int start = g_eoff[node];
    int deg   = g_count[node];

    float2 acc = *(const float2*)(bias + lane * 2);

    int j = 0;
    for (; j + 1 < deg; j += 2) {
        int2 r0 = g_edges[start + j];
        int2 r1 = g_edges[start + j + 1];
        float2 m0 = *(const float2*)(g_support + (long long)r0.x * F_OUT + lane * 2);
        float2 m1 = *(const float2*)(g_support + (long long)r1.x * F_OUT + lane * 2);
        float e0 = __int_as_float(r0.y);
        float e1 = __int_as_float(r1.y);
        acc.x = fmaf(e0, m0.x, acc.x);
        acc.y = fmaf(e0, m0.y, acc.y);
        acc.x = fmaf(e1, m1.x, acc.x);
        acc.y = fmaf(e1, m1.y, acc.y);
    }
    if (j < deg) {
        int2 r0 = g_edges[start + j];
        float2 m0 = *(const float2*)(g_support + (long long)r0.x * F_OUT + lane * 2);
        float e0 = __int_as_float(r0.y);
        acc.x = fmaf(e0, m0.x, acc.x);
        acc.y = fmaf(e0, m0.y, acc.y);
    }

    *(float2*)(out + (long long)node * F_OUT + lane * 2) = acc;
}

// ---------------------------------------------------------------------------
// Inputs (metadata order):
//   0: x [N,128] f32  1: t [N] f32  2: src [E]  3: dst [E]
//   4: edge_vals [E] f32  5: weight [128,64] f32  6: bias [64] f32
// Output: [N,64] f32
// ---------------------------------------------------------------------------
extern "C" void kernel_launch(void* const* d_in, const int* in_sizes, int n_in,
                              void* d_out, int out_size)
{
    const float* x    = (const float*)d_in[0];
    const float* t    = (const float*)d_in[1];
    const void*  src  = d_in[2];
    const void*  dst  = d_in[3];
    const float* ev   = (const float*)d_in[4];
    const float* w    = (const float*)d_in[5];
    const float* bias = (const float*)d_in[6];
    float*       out  = (float*)d_out;

    const int n = in_sizes[1];   // N
    const int e = in_sizes[2];   // E

    // 0) index dtype
    detect_idx_kernel<<<1, 32>>>((const long long*)src, n, e);

    // 1) zero counts
    zero_count_kernel<<<(n + 255) / 256, 256>>>(n);

    // 2) support = (x @ W) * t[:,None]
    gemm_scale_kernel<<<(n + GEMM_ROWS - 1) / GEMM_ROWS, GEMM_THREADS>>>(x, w, t, n);

    // 3) histogram of dst
    hist_kernel<<<(e + 255) / 256, 256>>>(dst, e);

    // 4-6) exclusive scan -> offsets + cursors
    int nb = (n + 1023) / 1024;
    scan1_kernel<<<nb, 1024>>>(n);
    scan2_kernel<<<1, 32>>>(nb);
    scan3_kernel<<<(n + 255) / 256, 256>>>(n);

    // 7) bucket edges by dst
    reorder_kernel<<<(e + 255) / 256, 256>>>(src, dst, ev, e);

    // 8) gather-reduce (writes bias too)
    gather_kernel<<<(n + 7) / 8, 256>>>(out, bias, n);
}

// round 13
// speedup vs baseline: 2.0238x; 1.1468x over previous
#include <cuda_runtime.h>

// Problem constants (dataset-fixed shapes)
#define F_IN   128
#define F_OUT  64
#define MAX_N  50000
#define MAX_E  800000

#define GEMM_ROWS   128
#define GEMM_THREADS 256

// ---------------- static scratch (no allocs allowed) ----------------
__device__ __align__(16) float g_support[MAX_N * F_OUT]; // (x@W)*t
__device__ __align__(16) int2  g_edges[MAX_E];           // (src, ev bits) bucketed by dst
__device__ int g_count[MAX_N];                           // per-dst degree
__device__ int g_eoff[MAX_N];                            // exclusive offsets
__device__ int g_cursor[MAX_N];                          // fill cursors
__device__ int g_bsum[64];                               // scan block sums
__device__ int g_boff[64];                               // scan block offsets
__device__ int g_idx_is64;                               // index dtype flag

// ---------------------------------------------------------------------------
// K0: index dtype detect (parallel). int32 buffers read as int64 produce
// values >= 2^32 almost surely for random indices.
// ---------------------------------------------------------------------------
__global__ void detect_idx_kernel(const long long* __restrict__ p, int n, int e)
{
    int cnt = (e < 32) ? e : 32;
    bool bad = false;
    if ((int)threadIdx.x < cnt) {
        long long v = p[threadIdx.x];
        bad = (v < 0 || v >= (long long)n);
    }
    unsigned m = __ballot_sync(0xffffffffu, bad);
    if (threadIdx.x == 0) g_idx_is64 = (m == 0u) ? 1 : 0;
}

__device__ __forceinline__ int load_idx(const void* p, int i)
{
    return g_idx_is64 ? (int)((const long long*)p)[i] : ((const int*)p)[i];
}

// ---------------------------------------------------------------------------
// K1: zero per-dst counts
// ---------------------------------------------------------------------------
__global__ void zero_count_kernel(int n)
{
    int i = blockIdx.x * blockDim.x + threadIdx.x;
    if (i < n) g_count[i] = 0;
}

// ---------------------------------------------------------------------------
// K2: GEMM + row-scale: support[r,:] = (x[r,:] @ W) * t[r]
// 256 threads -> 32 row-groups x 8 col-groups; 4 rows x 8 cols per thread.
// Runs on a forked stream, overlapped with the CSR build.
// ---------------------------------------------------------------------------
__global__ void __launch_bounds__(GEMM_THREADS)
gemm_scale_kernel(const float* __restrict__ x,
                  const float* __restrict__ w,
                  const float* __restrict__ t,
                  int n)
{
    __shared__ float ws[32 * F_OUT];           // 8 KB   (one K-phase of W)
    __shared__ float xs[GEMM_ROWS * 33];       // 16.9 KB (pad 33 -> conflict-free)

    const int tid  = threadIdx.x;
    const int row0 = blockIdx.x * GEMM_ROWS;
    const int cj = tid & 7;
    const int rg = tid >> 3;
    const int c0 = cj * 8;

    float acc[4][8];
    #pragma unroll
    for (int i = 0; i < 4; i++)
        #pragma unroll
        for (int j = 0; j < 8; j++) acc[i][j] = 0.0f;

    #pragma unroll
    for (int p = 0; p < 4; p++) {
        __syncthreads();
        {
            const float4* wsrc = (const float4*)(w + p * 32 * F_OUT);
            float4* wdst = (float4*)ws;
            wdst[tid]       = wsrc[tid];
            wdst[tid + 256] = wsrc[tid + 256];
        }
        #pragma unroll
        for (int i = 0; i < 4; i++) {
            int f  = tid + i * 256;
            int rr = f >> 3;
            int k4 = f & 7;
            int grow = row0 + rr;
            float4 v = make_float4(0.f, 0.f, 0.f, 0.f);
            if (grow < n)
                v = *(const float4*)(x + (long long)grow * F_IN + p * 32 + k4 * 4);
            float* d = xs + rr * 33 + k4 * 4;
            d[0] = v.x; d[1] = v.y; d[2] = v.z; d[3] = v.w;
        }
        __syncthreads();

        #pragma unroll 4
        for (int k = 0; k < 32; k++) {
            float4 w0 = *(const float4*)(ws + k * F_OUT + c0);
            float4 w1 = *(const float4*)(ws + k * F_OUT + c0 + 4);
            #pragma unroll
            for (int i = 0; i < 4; i++) {
                float xv = xs[(rg * 4 + i) * 33 + k];
                acc[i][0] = fmaf(xv, w0.x, acc[i][0]);
                acc[i][1] = fmaf(xv, w0.y, acc[i][1]);
                acc[i][2] = fmaf(xv, w0.z, acc[i][2]);
                acc[i][3] = fmaf(xv, w0.w, acc[i][3]);
                acc[i][4] = fmaf(xv, w1.x, acc[i][4]);
                acc[i][5] = fmaf(xv, w1.y, acc[i][5]);
                acc[i][6] = fmaf(xv, w1.z, acc[i][6]);
                acc[i][7] = fmaf(xv, w1.w, acc[i][7]);
            }
        }
    }

    #pragma unroll
    for (int i = 0; i < 4; i++) {
        int row = row0 + rg * 4 + i;
        if (row < n) {
            float tv = t[row];
            float4 o0 = make_float4(acc[i][0]*tv, acc[i][1]*tv, acc[i][2]*tv, acc[i][3]*tv);
            float4 o1 = make_float4(acc[i][4]*tv, acc[i][5]*tv, acc[i][6]*tv, acc[i][7]*tv);
            float4* op = (float4*)(g_support + (long long)row * F_OUT + c0);
            op[0] = o0;
            op[1] = o1;
        }
    }
}

// ---------------------------------------------------------------------------
// K3: per-dst histogram
// ---------------------------------------------------------------------------
__global__ void hist_kernel(const void* __restrict__ dst, int e)
{
    int i = blockIdx.x * blockDim.x + threadIdx.x;
    if (i < e) atomicAdd(&g_count[load_idx(dst, i)], 1);
}

// ---------------------------------------------------------------------------
// K4-K6: exclusive scan of g_count -> g_eoff (two-level)
// ---------------------------------------------------------------------------
__global__ void scan1_kernel(int n)
{
    __shared__ int sm[1024];
    int i = blockIdx.x * 1024 + threadIdx.x;
    int c = (i < n) ? g_count[i] : 0;
    sm[threadIdx.x] = c;
    __syncthreads();
    #pragma unroll
    for (int off = 1; off < 1024; off <<= 1) {
        int v = (threadIdx.x >= (unsigned)off) ? sm[threadIdx.x - off] : 0;
        __syncthreads();
        sm[threadIdx.x] += v;
        __syncthreads();
    }
    int incl = sm[threadIdx.x];
    if (i < n) g_eoff[i] = incl - c;          // block-local exclusive
    if (threadIdx.x == 1023) g_bsum[blockIdx.x] = incl;
}

// parallel block-sum scan (nb <= 64), shfl-based
__global__ void scan2_kernel(int nb)
{
    __shared__ int wtot;
    int tid  = threadIdx.x;          // 64 threads
    int lane = tid & 31;
    int wid  = tid >> 5;
    int v = (tid < nb) ? g_bsum[tid] : 0;
    int s = v;
    #pragma unroll
    for (int off = 1; off < 32; off <<= 1) {
        int u = __shfl_up_sync(0xffffffffu, s, off);
        if (lane >= off) s += u;
    }
    if (wid == 0 && lane == 31) wtot = s;
    __syncthreads();
    int incl = s + (wid == 1 ? wtot : 0);
    if (tid < nb) g_boff[tid] = incl - v;     // exclusive
}

__global__ void scan3_kernel(int n)
{
    int i = blockIdx.x * blockDim.x + threadIdx.x;
    if (i < n) {
        int e0 = g_eoff[i] + g_boff[i >> 10];
        g_eoff[i]   = e0;
        g_cursor[i] = e0;
    }
}

// ---------------------------------------------------------------------------
// K7: bucket edges by dst: g_edges[slot] = (src, ev)
// ---------------------------------------------------------------------------
__global__ void reorder_kernel(const void* __restrict__ src,
                               const void* __restrict__ dst,
                               const float* __restrict__ ev,
                               int e)
{
    int i = blockIdx.x * blockDim.x + threadIdx.x;
    if (i >= e) return;
    int s = load_idx(src, i);
    int d = load_idx(dst, i);
    int pos = atomicAdd(&g_cursor[d], 1);
    g_edges[pos] = make_int2(s, __float_as_int(ev[i]));
}

// ---------------------------------------------------------------------------
// K8: gather-reduce. One warp per dst node; lane owns 2 cols (float2).
// out[d,:] = sum_e ev_e * support[src_e,:] + bias. No atomics.
// ---------------------------------------------------------------------------
__global__ void __launch_bounds__(256)
gather_kernel(float* __restrict__ out,
              const float* __restrict__ bias,
              int n)
{
    int node = blockIdx.x * 8 + (threadIdx.x >> 5);
    if (node >= n) return;
    int lane = threadIdx.x & 31;

    int start = g_eoff[node];
    int deg   = g_count[node];

    float2 acc = *(const float2*)(bias + lane * 2);

    int j = 0;
    for (; j + 3 < deg; j += 4) {
        int2 r0 = g_edges[start + j];
        int2 r1 = g_edges[start + j + 1];
        int2 r2 = g_edges[start + j + 2];
        int2 r3 = g_edges[start + j + 3];
        float2 m0 = *(const float2*)(g_support + (long long)r0.x * F_OUT + lane * 2);
        float2 m1 = *(const float2*)(g_support + (long long)r1.x * F_OUT + lane * 2);
        float2 m2 = *(const float2*)(g_support + (long long)r2.x * F_OUT + lane * 2);
        float2 m3 = *(const float2*)(g_support + (long long)r3.x * F_OUT + lane * 2);
        float e0 = __int_as_float(r0.y), e1 = __int_as_float(r1.y);
        float e2 = __int_as_float(r2.y), e3 = __int_as_float(r3.y);
        acc.x = fmaf(e0, m0.x, acc.x);  acc.y = fmaf(e0, m0.y, acc.y);
        acc.x = fmaf(e1, m1.x, acc.x);  acc.y = fmaf(e1, m1.y, acc.y);
        acc.x = fmaf(e2, m2.x, acc.x);  acc.y = fmaf(e2, m2.y, acc.y);
        acc.x = fmaf(e3, m3.x, acc.x);  acc.y = fmaf(e3, m3.y, acc.y);
    }
    for (; j < deg; j++) {
        int2 r0 = g_edges[start + j];
        float2 m0 = *(const float2*)(g_support + (long long)r0.x * F_OUT + lane * 2);
        float e0 = __int_as_float(r0.y);
        acc.x = fmaf(e0, m0.x, acc.x);
        acc.y = fmaf(e0, m0.y, acc.y);
    }

    *(float2*)(out + (long long)node * F_OUT + lane * 2) = acc;
}

// ---------------------------------------------------------------------------
// Launch. Fork the (independent) GEMM onto a side stream so it overlaps the
// CSR build; join before gather. Stream/events are created once and cached —
// the captured GPU work is identical on every call.
//
// Inputs (metadata order):
//   0: x [N,128] f32  1: t [N] f32  2: src [E]  3: dst [E]
//   4: edge_vals [E] f32  5: weight [128,64] f32  6: bias [64] f32
// Output: [N,64] f32
// ---------------------------------------------------------------------------
extern "C" void kernel_launch(void* const* d_in, const int* in_sizes, int n_in,
                              void* d_out, int out_size)
{
    const float* x    = (const float*)d_in[0];
    const float* t    = (const float*)d_in[1];
    const void*  src  = d_in[2];
    const void*  dst  = d_in[3];
    const float* ev   = (const float*)d_in[4];
    const float* w    = (const float*)d_in[5];
    const float* bias = (const float*)d_in[6];
    float*       out  = (float*)d_out;

    const int n = in_sizes[1];   // N
    const int e = in_sizes[2];   // E

    static cudaStream_t s2 = nullptr;
    static cudaEvent_t  evFork = nullptr, evJoin = nullptr;
    if (!s2) {
        cudaStreamCreateWithFlags(&s2, cudaStreamNonBlocking);
        cudaEventCreateWithFlags(&evFork, cudaEventDisableTiming);
        cudaEventCreateWithFlags(&evJoin, cudaEventDisableTiming);
    }

    // ---- fork: GEMM branch (independent of edge processing) ----
    cudaEventRecord(evFork, 0);
    cudaStreamWaitEvent(s2, evFork, 0);
    gemm_scale_kernel<<<(n + GEMM_ROWS - 1) / GEMM_ROWS, GEMM_THREADS, 0, s2>>>(x, w, t, n);
    cudaEventRecord(evJoin, s2);

    // ---- main branch: CSR build ----
    detect_idx_kernel<<<1, 32>>>((const long long*)src, n, e);
    zero_count_kernel<<<(n + 255) / 256, 256>>>(n);
    hist_kernel<<<(e + 255) / 256, 256>>>(dst, e);

    int nb = (n + 1023) / 1024;
    scan1_kernel<<<nb, 1024>>>(n);
    scan2_kernel<<<1, 64>>>(nb);
    scan3_kernel<<<(n + 255) / 256, 256>>>(n);

    reorder_kernel<<<(e + 255) / 256, 256>>>(src, dst, ev, e);

    // ---- join, then gather ----
    cudaStreamWaitEvent(0, evJoin, 0);
    gather_kernel<<<(n + 7) / 8, 256>>>(out, bias, n);
}

// round 15
// speedup vs baseline: 2.0353x; 1.0057x over previous
#include <cuda_runtime.h>

// Problem constants (dataset-fixed shapes)
#define F_IN   128
#define F_OUT  64
#define MAX_N  50000
#define MAX_E  800000

#define GEMM_ROWS   128
#define GEMM_THREADS 256

// ---------------- static scratch (no allocs allowed) ----------------
__device__ __align__(16) float g_support[MAX_N * F_OUT]; // (x@W)*t
__device__ __align__(16) int2  g_edges[MAX_E];           // (src, ev bits) bucketed by dst
__device__ __align__(16) int g_count[MAX_N];             // per-dst degree
__device__ __align__(16) int g_eoff[MAX_N];              // exclusive offsets
__device__ __align__(16) int g_cursor[MAX_N];            // fill cursors
__device__ int g_bsum[64];                               // scan block totals
__device__ int g_idx_is64;                               // index dtype flag

// ---------------------------------------------------------------------------
// K0: zero counts + detect index dtype in one launch.
// int32 buffers read as int64 give values >= 2^32 almost surely.
// ---------------------------------------------------------------------------
__global__ void detect_zero_kernel(const long long* __restrict__ src64,
                                   int n, int e)
{
    int i = blockIdx.x * blockDim.x + threadIdx.x;
    if (i < n) g_count[i] = 0;
    if (blockIdx.x == 0 && threadIdx.x < 32) {
        int cnt = (e < 32) ? e : 32;
        bool bad = false;
        if ((int)threadIdx.x < cnt) {
            long long v = src64[threadIdx.x];
            bad = (v < 0 || v >= (long long)n);
        }
        unsigned m = __ballot_sync(0xffffffffu, bad);
        if (threadIdx.x == 0) g_idx_is64 = (m == 0u) ? 1 : 0;
    }
}

__device__ __forceinline__ int load_idx(const void* p, int i)
{
    return g_idx_is64 ? (int)((const long long*)p)[i] : ((const int*)p)[i];
}

// ---------------------------------------------------------------------------
// K1 (side stream): GEMM + row-scale: support[r,:] = (x[r,:] @ W) * t[r]
// ---------------------------------------------------------------------------
__global__ void __launch_bounds__(GEMM_THREADS)
gemm_scale_kernel(const float* __restrict__ x,
                  const float* __restrict__ w,
                  const float* __restrict__ t,
                  int n)
{
    __shared__ float ws[32 * F_OUT];           // 8 KB   (one K-phase of W)
    __shared__ float xs[GEMM_ROWS * 33];       // 16.9 KB (pad -> conflict-free)

    const int tid  = threadIdx.x;
    const int row0 = blockIdx.x * GEMM_ROWS;
    const int cj = tid & 7;
    const int rg = tid >> 3;
    const int c0 = cj * 8;

    float acc[4][8];
    #pragma unroll
    for (int i = 0; i < 4; i++)
        #pragma unroll
        for (int j = 0; j < 8; j++) acc[i][j] = 0.0f;

    #pragma unroll
    for (int p = 0; p < 4; p++) {
        __syncthreads();
        {
            const float4* wsrc = (const float4*)(w + p * 32 * F_OUT);
            float4* wdst = (float4*)ws;
            wdst[tid]       = wsrc[tid];
            wdst[tid + 256] = wsrc[tid + 256];
        }
        #pragma unroll
        for (int i = 0; i < 4; i++) {
            int f  = tid + i * 256;
            int rr = f >> 3;
            int k4 = f & 7;
            int grow = row0 + rr;
            float4 v = make_float4(0.f, 0.f, 0.f, 0.f);
            if (grow < n)
                v = *(const float4*)(x + (long long)grow * F_IN + p * 32 + k4 * 4);
            float* d = xs + rr * 33 + k4 * 4;
            d[0] = v.x; d[1] = v.y; d[2] = v.z; d[3] = v.w;
        }
        __syncthreads();

        #pragma unroll 4
        for (int k = 0; k < 32; k++) {
            float4 w0 = *(const float4*)(ws + k * F_OUT + c0);
            float4 w1 = *(const float4*)(ws + k * F_OUT + c0 + 4);
            #pragma unroll
            for (int i = 0; i < 4; i++) {
                float xv = xs[(rg * 4 + i) * 33 + k];
                acc[i][0] = fmaf(xv, w0.x, acc[i][0]);
                acc[i][1] = fmaf(xv, w0.y, acc[i][1]);
                acc[i][2] = fmaf(xv, w0.z, acc[i][2]);
                acc[i][3] = fmaf(xv, w0.w, acc[i][3]);
                acc[i][4] = fmaf(xv, w1.x, acc[i][4]);
                acc[i][5] = fmaf(xv, w1.y, acc[i][5]);
                acc[i][6] = fmaf(xv, w1.z, acc[i][6]);
                acc[i][7] = fmaf(xv, w1.w, acc[i][7]);
            }
        }
    }

    #pragma unroll
    for (int i = 0; i < 4; i++) {
        int row = row0 + rg * 4 + i;
        if (row < n) {
            float tv = t[row];
            float4 o0 = make_float4(acc[i][0]*tv, acc[i][1]*tv, acc[i][2]*tv, acc[i][3]*tv);
            float4 o1 = make_float4(acc[i][4]*tv, acc[i][5]*tv, acc[i][6]*tv, acc[i][7]*tv);
            float4* op = (float4*)(g_support + (long long)row * F_OUT + c0);
            op[0] = o0;
            op[1] = o1;
        }
    }
}

// ---------------------------------------------------------------------------
// K2: per-dst histogram, 4 edges/thread with vector index loads (MLP=4)
// ---------------------------------------------------------------------------
__global__ void __launch_bounds__(256)
hist_kernel(const void* __restrict__ dst, int e)
{
    int base = (blockIdx.x * blockDim.x + threadIdx.x) << 2;
    if (base >= e) return;
    int rem = e - base;

    int d0, d1 = -1, d2 = -1, d3 = -1;
    if (rem >= 4) {
        if (g_idx_is64) {
            const longlong2* p = (const longlong2*)((const long long*)dst + base);
            longlong2 a = p[0], b = p[1];
            d0 = (int)a.x; d1 = (int)a.y; d2 = (int)b.x; d3 = (int)b.y;
        } else {
            int4 v = *(const int4*)((const int*)dst + base);
            d0 = v.x; d1 = v.y; d2 = v.z; d3 = v.w;
        }
    } else {
        d0 = load_idx(dst, base);
        if (rem > 1) d1 = load_idx(dst, base + 1);
        if (rem > 2) d2 = load_idx(dst, base + 2);
    }

    atomicAdd(&g_count[d0], 1);
    if (d1 >= 0) atomicAdd(&g_count[d1], 1);
    if (d2 >= 0) atomicAdd(&g_count[d2], 1);
    if (d3 >= 0) atomicAdd(&g_count[d3], 1);
}

// ---------------------------------------------------------------------------
// K3: block scan (256 threads x 4 items = 1024 per block), shfl-based.
// Writes block-local exclusive prefixes + per-block totals.
// ---------------------------------------------------------------------------
__global__ void __launch_bounds__(256)
scan1_kernel(int n)
{
    __shared__ int wsum[8];
    int t = threadIdx.x;
    int gi = blockIdx.x * 1024 + t * 4;

    int4 c = make_int4(0, 0, 0, 0);
    if (gi + 3 < n) {
        c = *(const int4*)&g_count[gi];
    } else if (gi < n) {
        c.x = g_count[gi];
        if (gi + 1 < n) c.y = g_count[gi + 1];
        if (gi + 2 < n) c.z = g_count[gi + 2];
    }
    int s3 = c.x + c.y + c.z + c.w;

    int lane = t & 31, wid = t >> 5;
    int ws = s3;
    #pragma unroll
    for (int off = 1; off < 32; off <<= 1) {
        int u = __shfl_up_sync(0xffffffffu, ws, off);
        if (lane >= off) ws += u;
    }
    if (lane == 31) wsum[wid] = ws;
    __syncthreads();
    if (t == 0) {
        int run = 0;
        #pragma unroll
        for (int j = 0; j < 8; j++) { int v = wsum[j]; wsum[j] = run; run += v; }
        g_bsum[blockIdx.x] = run;
    }
    __syncthreads();

    int excl = wsum[wid] + (ws - s3);      // exclusive prefix for this thread
    if (gi < n) {
        g_eoff[gi] = excl;
        if (gi + 1 < n) g_eoff[gi + 1] = excl + c.x;
        if (gi + 2 < n) g_eoff[gi + 2] = excl + c.x + c.y;
        if (gi + 3 < n) g_eoff[gi + 3] = excl + c.x + c.y + c.z;
    }
}

// ---------------------------------------------------------------------------
// K4: add block offsets (each block reduces its own prefix from g_bsum)
// and initialize cursors. Replaces separate scan2+scan3.
// ---------------------------------------------------------------------------
__global__ void __launch_bounds__(256)
scan3_kernel(int n)
{
    __shared__ int s_off;
    int chunk = blockIdx.x >> 2;           // which 1024-chunk this block is in
    if (threadIdx.x < 32) {
        int v = 0;
        for (int j = (int)threadIdx.x; j < chunk; j += 32) v += g_bsum[j];
        #pragma unroll
        for (int off = 16; off; off >>= 1)
            v += __shfl_down_sync(0xffffffffu, v, off);
        if (threadIdx.x == 0) s_off = v;
    }
    __syncthreads();
    int i = blockIdx.x * 256 + threadIdx.x;
    if (i < n) {
        int e0 = g_eoff[i] + s_off;
        g_eoff[i]   = e0;
        g_cursor[i] = e0;
    }
}

// ---------------------------------------------------------------------------
// K5: bucket edges by dst, 4 edges/thread, vector loads.
// ---------------------------------------------------------------------------
__global__ void __launch_bounds__(256)
reorder_kernel(const void* __restrict__ src,
               const void* __restrict__ dst,
               const float* __restrict__ ev,
               int e)
{
    int base = (blockIdx.x * blockDim.x + threadIdx.x) << 2;
    if (base >= e) return;
    int rem = e - base;

    int s[4], d[4];
    float v[4];
    int cnt;
    if (rem >= 4) {
        cnt = 4;
        if (g_idx_is64) {
            const longlong2* ps = (const longlong2*)((const long long*)src + base);
            const longlong2* pd = (const longlong2*)((const long long*)dst + base);
            longlong2 a = ps[0], b = ps[1];
            longlong2 c = pd[0], f = pd[1];
            s[0] = (int)a.x; s[1] = (int)a.y; s[2] = (int)b.x; s[3] = (int)b.y;
            d[0] = (int)c.x; d[1] = (int)c.y; d[2] = (int)f.x; d[3] = (int)f.y;
        } else {
            int4 a = *(const int4*)((const int*)src + base);
            int4 c = *(const int4*)((const int*)dst + base);
            s[0] = a.x; s[1] = a.y; s[2] = a.z; s[3] = a.w;
            d[0] = c.x; d[1] = c.y; d[2] = c.z; d[3] = c.w;
        }
        float4 vv = *(const float4*)(ev + base);
        v[0] = vv.x; v[1] = vv.y; v[2] = vv.z; v[3] = vv.w;
    } else {
        cnt = rem;
        for (int j = 0; j < rem; j++) {
            s[j] = load_idx(src, base + j);
            d[j] = load_idx(dst, base + j);
            v[j] = ev[base + j];
        }
    }

    #pragma unroll
    for (int j = 0; j < 4; j++) {
        if (j < cnt) {
            int pos = atomicAdd(&g_cursor[d[j]], 1);
            g_edges[pos] = make_int2(s[j], __float_as_int(v[j]));
        }
    }
}

// ---------------------------------------------------------------------------
// K6: gather-reduce. One warp per dst node; lane owns 2 cols (float2).
// out[d,:] = sum_e ev_e * support[src_e,:] + bias. No atomics.
// ---------------------------------------------------------------------------
__global__ void __launch_bounds__(256)
gather_kernel(float* __restrict__ out,
              const float* __restrict__ bias,
              int n)
{
    int node = blockIdx.x * 8 + (threadIdx.x >> 5);
    if (node >= n) return;
    int lane = threadIdx.x & 31;

    int start = g_eoff[node];
    int deg   = g_count[node];

    float2 acc = *(const float2*)(bias + lane * 2);

    int j = 0;
    for (; j + 3 < deg; j += 4) {
        int2 r0 = g_edges[start + j];
        int2 r1 = g_edges[start + j + 1];
        int2 r2 = g_edges[start + j + 2];
        int2 r3 = g_edges[start + j + 3];
        float2 m0 = *(const float2*)(g_support + (long long)r0.x * F_OUT + lane * 2);
        float2 m1 = *(const float2*)(g_support + (long long)r1.x * F_OUT + lane * 2);
        float2 m2 = *(const float2*)(g_support + (long long)r2.x * F_OUT + lane * 2);
        float2 m3 = *(const float2*)(g_support + (long long)r3.x * F_OUT + lane * 2);
        float e0 = __int_as_float(r0.y), e1 = __int_as_float(r1.y);
        float e2 = __int_as_float(r2.y), e3 = __int_as_float(r3.y);
        acc.x = fmaf(e0, m0.x, acc.x);  acc.y = fmaf(e0, m0.y, acc.y);
        acc.x = fmaf(e1, m1.x, acc.x);  acc.y = fmaf(e1, m1.y, acc.y);
        acc.x = fmaf(e2, m2.x, acc.x);  acc.y = fmaf(e2, m2.y, acc.y);
        acc.x = fmaf(e3, m3.x, acc.x);  acc.y = fmaf(e3, m3.y, acc.y);
    }
    for (; j < deg; j++) {
        int2 r0 = g_edges[start + j];
        float2 m0 = *(const float2*)(g_support + (long long)r0.x * F_OUT + lane * 2);
        float e0 = __int_as_float(r0.y);
        acc.x = fmaf(e0, m0.x, acc.x);
        acc.y = fmaf(e0, m0.y, acc.y);
    }

    *(float2*)(out + (long long)node * F_OUT + lane * 2) = acc;
}

// ---------------------------------------------------------------------------
// Launch. GEMM forked onto a side stream, overlapping the CSR build; join
// before gather. Stream/events cached; captured work identical every call.
//
// Inputs (metadata order):
//   0: x [N,128] f32  1: t [N] f32  2: src [E]  3: dst [E]
//   4: edge_vals [E] f32  5: weight [128,64] f32  6: bias [64] f32
// Output: [N,64] f32
// ---------------------------------------------------------------------------
extern "C" void kernel_launch(void* const* d_in, const int* in_sizes, int n_in,
                              void* d_out, int out_size)
{
    const float* x    = (const float*)d_in[0];
    const float* t    = (const float*)d_in[1];
    const void*  src  = d_in[2];
    const void*  dst  = d_in[3];
    const float* ev   = (const float*)d_in[4];
    const float* w    = (const float*)d_in[5];
    const float* bias = (const float*)d_in[6];
    float*       out  = (float*)d_out;

    const int n = in_sizes[1];   // N
    const int e = in_sizes[2];   // E

    static cudaStream_t s2 = nullptr;
    static cudaEvent_t  evFork = nullptr, evJoin = nullptr;
    if (!s2) {
        cudaStreamCreateWithFlags(&s2, cudaStreamNonBlocking);
        cudaEventCreateWithFlags(&evFork, cudaEventDisableTiming);
        cudaEventCreateWithFlags(&evJoin, cudaEventDisableTiming);
    }

    // ---- fork: GEMM branch (independent of edge processing) ----
    cudaEventRecord(evFork, 0);
    cudaStreamWaitEvent(s2, evFork, 0);
    gemm_scale_kernel<<<(n + GEMM_ROWS - 1) / GEMM_ROWS, GEMM_THREADS, 0, s2>>>(x, w, t, n);
    cudaEventRecord(evJoin, s2);

    // ---- main branch: CSR build ----
    detect_zero_kernel<<<(n + 255) / 256, 256>>>((const long long*)src, n, e);

    int e4 = (e + 3) / 4;
    hist_kernel<<<(e4 + 255) / 256, 256>>>(dst, e);

    int nb = (n + 1023) / 1024;
    scan1_kernel<<<nb, 256>>>(n);
    scan3_kernel<<<(n + 255) / 256, 256>>>(n);

    reorder_kernel<<<(e4 + 255) / 256, 256>>>(src, dst, ev, e);

    // ---- join, then gather ----
    cudaStreamWaitEvent(0, evJoin, 0);
    gather_kernel<<<(n + 7) / 8, 256>>>(out, bias, n);
}